// round 8
// baseline (speedup 1.0000x reference)
#include <cuda_runtime.h>
#include <cfloat>

#define NN 50000
#define NE 600000
#define D  128
#define NB 8

// ---------------- scratch (static device memory; no allocs) ----------------
__device__ float g_z [NN * D];
__device__ float g_u [NN * D];
__device__ float g_v [NN * D];
__device__ float g_h1[NN * D];
__device__ float g_sum[4 * D];
__device__ float g_ss [4 * D];
__device__ float g_pool[3 * NB * D];
__device__ float g_whi[4 * D * D];   // tf32-hi of the 4 conv weights
__device__ float g_wlo[4 * D * D];   // tf32-lo residual

__device__ __forceinline__ void atomicMaxFloat(float* addr, float v) {
    if (v >= 0.f) atomicMax((int*)addr, __float_as_int(v));
    else          atomicMin((unsigned int*)addr, __float_as_uint(v));
}

__device__ __forceinline__ void cp16(void* smem, const void* g, int srcsize) {
    unsigned s = (unsigned)__cvta_generic_to_shared(smem);
    asm volatile("cp.async.cg.shared.global [%0], [%1], 16, %2;"
                 :: "r"(s), "l"(g), "r"(srcsize));
}
__device__ __forceinline__ unsigned f2tf32(float v) {
    unsigned r;
    asm("cvt.rna.tf32.f32 %0, %1;" : "=r"(r) : "f"(v));
    return r;
}
__device__ __forceinline__ void mma_tf32(float* d, const unsigned* a,
                                         unsigned b0, unsigned b1) {
    asm volatile(
        "mma.sync.aligned.m16n8k8.row.col.f32.tf32.tf32.f32 "
        "{%0,%1,%2,%3}, {%4,%5,%6,%7}, {%8,%9}, {%0,%1,%2,%3};"
        : "+f"(d[0]), "+f"(d[1]), "+f"(d[2]), "+f"(d[3])
        : "r"(a[0]), "r"(a[1]), "r"(a[2]), "r"(a[3]), "r"(b0), "r"(b1));
}

// ---------------- init: zero stats, pool = -FLT_MAX ----------------
__global__ void k_init() {
    int t = threadIdx.x;
    if (t < 4 * D) { g_sum[t] = 0.f; g_ss[t] = 0.f; }
    for (int i = t; i < 3 * NB * D; i += 1024) g_pool[i] = -FLT_MAX;
}

// ---------------- split one 128x128 weight into tf32 hi/lo -----------------
__global__ __launch_bounds__(256) void k_wsplit(const float* __restrict__ w,
                                                float* __restrict__ whi,
                                                float* __restrict__ wlo) {
    int i = (blockIdx.x * 256 + threadIdx.x) * 4;
    float4 v = *(const float4*)(w + i);
    float4 hi, lo;
    hi.x = __uint_as_float(f2tf32(v.x)); lo.x = __uint_as_float(f2tf32(v.x - hi.x));
    hi.y = __uint_as_float(f2tf32(v.y)); lo.y = __uint_as_float(f2tf32(v.y - hi.y));
    hi.z = __uint_as_float(f2tf32(v.z)); lo.z = __uint_as_float(f2tf32(v.z - hi.z));
    hi.w = __uint_as_float(f2tf32(v.w)); lo.w = __uint_as_float(f2tf32(v.w - hi.w));
    *(float4*)(whi + i) = hi;
    *(float4*)(wlo + i) = lo;
}

// ------- scatter: z[dst] += x[src]; warp per 4 edges, red.global.v4 --------
#define EPW 4
__global__ __launch_bounds__(256) void k_scatter(const float* __restrict__ x,
                                                 const int* __restrict__ src,
                                                 const int* __restrict__ dst) {
    int warp = (blockIdx.x * 256 + threadIdx.x) >> 5;
    int lane = threadIdx.x & 31;
    int e0   = warp * EPW;
    int4 s4 = *(const int4*)(src + e0);
    int4 d4 = *(const int4*)(dst + e0);
    int ss[EPW] = {s4.x, s4.y, s4.z, s4.w};
    int dd[EPW] = {d4.x, d4.y, d4.z, d4.w};
    float4 v[EPW];
#pragma unroll
    for (int i = 0; i < EPW; i++)
        v[i] = *(const float4*)(x + (size_t)ss[i] * D + lane * 4);
#pragma unroll
    for (int i = 0; i < EPW; i++) {
        float* p = g_z + (size_t)dd[i] * D + lane * 4;
        asm volatile("red.global.add.v4.f32 [%0], {%1, %2, %3, %4};"
                     :: "l"(p), "f"(v[i].x), "f"(v[i].y), "f"(v[i].z), "f"(v[i].w)
                     : "memory");
    }
}

// --------- 3xTF32 tensor-core GEMM: 128 rows x 128 cols per block ----------
// bnrelu=0: out = A @ W + bias
// bnrelu=1: out = relu(bn(A)) @ W + bias
// Column sum/sumsq of output accumulated into out_sum/out_ss.
#define ASTRIDE 20
#define WSTRIDE 136
#define NCHUNK  8
#define SM_AS   (2 * 128 * ASTRIDE)          // 5120 floats
#define SM_W    (2 * 16 * WSTRIDE)           // 4352 floats each for hi/lo
#define SM_TOTAL ((SM_AS + 2 * SM_W + 256) * 4)  // bytes = 56320
__global__ __launch_bounds__(256) void k_gemm(
    const float* __restrict__ A,
    const float* __restrict__ Whi, const float* __restrict__ Wlo,
    const float* __restrict__ bias, float* __restrict__ out,
    const float* __restrict__ in_sum, const float* __restrict__ in_ss,
    const float* __restrict__ gamma, const float* __restrict__ beta,
    float* __restrict__ out_sum, float* __restrict__ out_ss,
    int bnrelu)
{
    extern __shared__ float sdyn[];
    float* As    = sdyn;
    float* Whi_s = sdyn + SM_AS;
    float* Wlo_s = Whi_s + SM_W;
    float* sc_s  = Wlo_s + SM_W;
    float* sh_s  = sc_s + 128;

    const int tid  = threadIdx.x;
    const int wid  = tid >> 5;
    const int lane = tid & 31;
    const int gid  = lane >> 2;
    const int qid  = lane & 3;
    const int wm   = (wid >> 1) * 32;
    const int wn   = (wid & 1) * 64;
    const int row0 = blockIdx.x * 128;

    if (bnrelu && tid < 128) {
        float m   = in_sum[tid] * (1.0f / NN);
        float var = in_ss[tid] * (1.0f / NN) - m * m;
        float rs  = rsqrtf(var + 1e-5f);
        float sc  = gamma[tid] * rs;
        sc_s[tid] = sc;
        sh_s[tid] = fmaf(-m, sc, beta[tid]);
    }

    float acc[2][8][4];
#pragma unroll
    for (int mt = 0; mt < 2; mt++)
#pragma unroll
        for (int nt = 0; nt < 8; nt++)
#pragma unroll
            for (int j = 0; j < 4; j++) acc[mt][nt][j] = 0.f;

    const int a_r  = tid >> 2;
    const int a_c4 = (tid & 3) * 4;
    const int w_r  = tid >> 5;
    const int w_c4 = (tid & 31) * 4;

#define LOAD_CHUNK(c, b)                                                        \
    {                                                                           \
        _Pragma("unroll")                                                       \
        for (int p = 0; p < 2; p++) {                                           \
            int r = a_r + p * 64;                                               \
            int gr = row0 + r;                                                  \
            const float* gp = A + (size_t)(gr < NN ? gr : 0) * D + (c)*16 + a_c4; \
            cp16(&As[(b) * (128 * ASTRIDE) + r * ASTRIDE + a_c4], gp, gr < NN ? 16 : 0); \
        }                                                                       \
        _Pragma("unroll")                                                       \
        for (int p = 0; p < 2; p++) {                                           \
            int r = w_r + p * 8;                                                \
            cp16(&Whi_s[(b) * (16 * WSTRIDE) + r * WSTRIDE + w_c4],             \
                 Whi + (size_t)((c)*16 + r) * D + w_c4, 16);                    \
            cp16(&Wlo_s[(b) * (16 * WSTRIDE) + r * WSTRIDE + w_c4],             \
                 Wlo + (size_t)((c)*16 + r) * D + w_c4, 16);                    \
        }                                                                       \
        asm volatile("cp.async.commit_group;");                                 \
    }

    LOAD_CHUNK(0, 0);

    for (int c = 0; c < NCHUNK; c++) {
        if (c + 1 < NCHUNK) {
            LOAD_CHUNK(c + 1, (c + 1) & 1);
            asm volatile("cp.async.wait_group 1;");
        } else {
            asm volatile("cp.async.wait_group 0;");
        }
        __syncthreads();
        const float* Ab = As + (c & 1) * (128 * ASTRIDE);
        const float* Wh = Whi_s + (c & 1) * (16 * WSTRIDE);
        const float* Wl = Wlo_s + (c & 1) * (16 * WSTRIDE);
#pragma unroll
        for (int k8 = 0; k8 < 2; k8++) {
            const int k0 = k8 * 8;
            const int cA = k0 + qid;
            unsigned afh[2][4], afl[2][4];
            float sc0 = 1.f, sh0 = 0.f, sc1 = 1.f, sh1 = 0.f;
            if (bnrelu) {
                int kg = c * 16 + cA;
                sc0 = sc_s[kg];     sh0 = sh_s[kg];
                sc1 = sc_s[kg + 4]; sh1 = sh_s[kg + 4];
            }
#pragma unroll
            for (int mt = 0; mt < 2; mt++) {
                int r = wm + 16 * mt + gid;
                float f[4];
                f[0] = Ab[r * ASTRIDE + cA];
                f[1] = Ab[(r + 8) * ASTRIDE + cA];
                f[2] = Ab[r * ASTRIDE + cA + 4];
                f[3] = Ab[(r + 8) * ASTRIDE + cA + 4];
                if (bnrelu) {
                    f[0] = fmaxf(fmaf(f[0], sc0, sh0), 0.f);
                    f[1] = fmaxf(fmaf(f[1], sc0, sh0), 0.f);
                    f[2] = fmaxf(fmaf(f[2], sc1, sh1), 0.f);
                    f[3] = fmaxf(fmaf(f[3], sc1, sh1), 0.f);
                }
#pragma unroll
                for (int j = 0; j < 4; j++) {
                    unsigned hb = f2tf32(f[j]);
                    afh[mt][j] = hb;
                    afl[mt][j] = f2tf32(f[j] - __uint_as_float(hb));
                }
            }
#pragma unroll
            for (int nt = 0; nt < 8; nt++) {
                int cB = wn + nt * 8 + gid;
                unsigned bh0 = __float_as_uint(Wh[(k0 + qid) * WSTRIDE + cB]);
                unsigned bh1 = __float_as_uint(Wh[(k0 + qid + 4) * WSTRIDE + cB]);
                unsigned bl0 = __float_as_uint(Wl[(k0 + qid) * WSTRIDE + cB]);
                unsigned bl1 = __float_as_uint(Wl[(k0 + qid + 4) * WSTRIDE + cB]);
#pragma unroll
                for (int mt = 0; mt < 2; mt++) {
                    mma_tf32(acc[mt][nt], afl[mt], bh0, bh1);
                    mma_tf32(acc[mt][nt], afh[mt], bl0, bl1);
                    mma_tf32(acc[mt][nt], afh[mt], bh0, bh1);
                }
            }
        }
        __syncthreads();
    }

    // ---- epilogue: bias, store, column stats ----
#pragma unroll
    for (int nt = 0; nt < 8; nt++) {
        int col = wn + nt * 8 + 2 * qid;
        float2 bb = *(const float2*)(bias + col);
        float s0 = 0.f, s1 = 0.f, q0 = 0.f, q1 = 0.f;
#pragma unroll
        for (int mt = 0; mt < 2; mt++) {
            int r = row0 + wm + 16 * mt + gid;
            float v0 = acc[mt][nt][0] + bb.x;
            float v1 = acc[mt][nt][1] + bb.y;
            float v2 = acc[mt][nt][2] + bb.x;
            float v3 = acc[mt][nt][3] + bb.y;
            if (r < NN) {
                *(float2*)(out + (size_t)r * D + col) = make_float2(v0, v1);
                s0 += v0; s1 += v1; q0 += v0 * v0; q1 += v1 * v1;
            }
            if (r + 8 < NN) {
                *(float2*)(out + (size_t)(r + 8) * D + col) = make_float2(v2, v3);
                s0 += v2; s1 += v3; q0 += v2 * v2; q1 += v3 * v3;
            }
        }
#pragma unroll
        for (int m = 4; m < 32; m <<= 1) {
            s0 += __shfl_xor_sync(0xffffffffu, s0, m);
            s1 += __shfl_xor_sync(0xffffffffu, s1, m);
            q0 += __shfl_xor_sync(0xffffffffu, q0, m);
            q1 += __shfl_xor_sync(0xffffffffu, q1, m);
        }
        if (lane < 4) {
            atomicAdd(&out_sum[col], s0);
            atomicAdd(&out_sum[col + 1], s1);
            atomicAdd(&out_ss[col], q0);
            atomicAdd(&out_ss[col + 1], q1);
        }
    }
}

// -- y = leaky_relu(bn(v)); write y (+ optional znext=(1+eps)*y); pooling ---
__global__ __launch_bounds__(256) void k_out(
    const float* __restrict__ v, const float* __restrict__ in_sum,
    const float* __restrict__ in_ss, const float* __restrict__ gamma,
    const float* __restrict__ beta, float* __restrict__ y,
    float* __restrict__ pool, const int* __restrict__ seg,
    float* __restrict__ znext, const float* __restrict__ eps_next)
{
    __shared__ float sc_s[128], sh_s[128];
    __shared__ int seg_s[128];
    int tid  = threadIdx.x;
    int row0 = blockIdx.x * 128;
    if (tid < 128) {
        float m   = in_sum[tid] * (1.0f / NN);
        float var = in_ss[tid] * (1.0f / NN) - m * m;
        float rs  = rsqrtf(var + 1e-5f);
        float sc  = gamma[tid] * rs;
        sc_s[tid] = sc;
        sh_s[tid] = fmaf(-m, sc, beta[tid]);
        int r = row0 + tid;
        seg_s[tid] = (r < NN) ? seg[r] : -1;
    }
    __syncthreads();
    float es = znext ? (1.0f + *eps_next) : 0.f;
    int c    = tid & 127;
    int rbeg = (tid >> 7) * 64;
    float sc = sc_s[c], sh = sh_s[c];
    float runmax = -FLT_MAX;
    int cur = -1;
    for (int i = 0; i < 64; i++) {
        int r = rbeg + i, gr = row0 + r;
        if (gr >= NN) break;
        float val = fmaf(v[(size_t)gr * D + c], sc, sh);
        val = (val > 0.f) ? val : val * 0.01f;
        y[(size_t)gr * D + c] = val;
        if (znext) znext[(size_t)gr * D + c] = es * val;
        int s = seg_s[r];
        if (s != cur) {
            if (cur >= 0) atomicMaxFloat(&pool[cur * D + c], runmax);
            cur = s; runmax = val;
        } else runmax = fmaxf(runmax, val);
    }
    if (cur >= 0) atomicMaxFloat(&pool[cur * D + c], runmax);
}

// ------ segment-max pooling of raw input h + z init for layer 0 ------------
__global__ __launch_bounds__(256) void k_pool0(const float* __restrict__ x,
                                               const int* __restrict__ seg,
                                               float* __restrict__ pool,
                                               float* __restrict__ z,
                                               const float* __restrict__ epsp)
{
    __shared__ int seg_s[128];
    int tid  = threadIdx.x;
    int row0 = blockIdx.x * 128;
    if (tid < 128) { int r = row0 + tid; seg_s[tid] = (r < NN) ? seg[r] : -1; }
    __syncthreads();
    float es = 1.0f + *epsp;
    int c    = tid & 127;
    int rbeg = (tid >> 7) * 64;
    float runmax = -FLT_MAX;
    int cur = -1;
    for (int i = 0; i < 64; i++) {
        int r = rbeg + i, gr = row0 + r;
        if (gr >= NN) break;
        float val = x[(size_t)gr * D + c];
        z[(size_t)gr * D + c] = es * val;
        int s = seg_s[r];
        if (s != cur) {
            if (cur >= 0) atomicMaxFloat(&pool[cur * D + c], runmax);
            cur = s; runmax = val;
        } else runmax = fmaxf(runmax, val);
    }
    if (cur >= 0) atomicMaxFloat(&pool[cur * D + c], runmax);
}

// -------- score = sum_l pooled_l @ pW_l + pb_l  (8x128, one block) ---------
__global__ __launch_bounds__(256) void k_score(
    const float* __restrict__ W0, const float* __restrict__ b0,
    const float* __restrict__ W1, const float* __restrict__ b1,
    const float* __restrict__ W2, const float* __restrict__ b2,
    float* __restrict__ out)
{
    __shared__ float ps[3 * NB * D];
    int tid = threadIdx.x;
    for (int i = tid; i < 3 * NB * D; i += 256) ps[i] = g_pool[i];
    __syncthreads();
    int b  = tid >> 5;
    int j0 = (tid & 31) * 4;
    float acc[4];
#pragma unroll
    for (int j = 0; j < 4; j++) acc[j] = b0[j0 + j] + b1[j0 + j] + b2[j0 + j];
    const float* Ws[3] = {W0, W1, W2};
    for (int l = 0; l < 3; l++) {
        const float* pl = ps + (l * NB + b) * D;
        const float* Wl = Ws[l];
        for (int k = 0; k < D; k++) {
            float p = pl[k];
            float4 w = *(const float4*)(Wl + (size_t)k * D + j0);
            acc[0] = fmaf(p, w.x, acc[0]);
            acc[1] = fmaf(p, w.y, acc[1]);
            acc[2] = fmaf(p, w.z, acc[2]);
            acc[3] = fmaf(p, w.w, acc[3]);
        }
    }
#pragma unroll
    for (int j = 0; j < 4; j++) out[b * D + j0 + j] = acc[j];
}

// ---------------------------------------------------------------------------
extern "C" void kernel_launch(void* const* d_in, const int* in_sizes, int n_in,
                              void* d_out, int out_size)
{
    const float* h   = (const float*)d_in[0];
    const int*   src = (const int*)d_in[1];
    const int*   dst = (const int*)d_in[2];
    const int*   seg = (const int*)d_in[3];
    const float* c_eps[2] = {(const float*)d_in[4],  (const float*)d_in[13]};
    const float* c_W1 [2] = {(const float*)d_in[5],  (const float*)d_in[14]};
    const float* c_b1 [2] = {(const float*)d_in[6],  (const float*)d_in[15]};
    const float* c_g1 [2] = {(const float*)d_in[7],  (const float*)d_in[16]};
    const float* c_be1[2] = {(const float*)d_in[8],  (const float*)d_in[17]};
    const float* c_W2 [2] = {(const float*)d_in[9],  (const float*)d_in[18]};
    const float* c_b2 [2] = {(const float*)d_in[10], (const float*)d_in[19]};
    const float* c_g2 [2] = {(const float*)d_in[11], (const float*)d_in[20]};
    const float* c_be2[2] = {(const float*)d_in[12], (const float*)d_in[21]};
    const float* pW[3] = {(const float*)d_in[22], (const float*)d_in[24], (const float*)d_in[26]};
    const float* pb[3] = {(const float*)d_in[23], (const float*)d_in[25], (const float*)d_in[27]};

    float* out_h2 = (float*)d_out;
    float* out_sc = (float*)d_out + (size_t)NN * D;

    float *z, *u, *v, *h1, *sums, *sss, *pool, *whi, *wlo;
    cudaGetSymbolAddress((void**)&z,    g_z);
    cudaGetSymbolAddress((void**)&u,    g_u);
    cudaGetSymbolAddress((void**)&v,    g_v);
    cudaGetSymbolAddress((void**)&h1,   g_h1);
    cudaGetSymbolAddress((void**)&sums, g_sum);
    cudaGetSymbolAddress((void**)&sss,  g_ss);
    cudaGetSymbolAddress((void**)&pool, g_pool);
    cudaGetSymbolAddress((void**)&whi,  g_whi);
    cudaGetSymbolAddress((void**)&wlo,  g_wlo);

    cudaFuncSetAttribute(k_gemm, cudaFuncAttributeMaxDynamicSharedMemorySize,
                         SM_TOTAL);

    const int GEMM_BLOCKS = (NN + 127) / 128;   // 391
    const int ROW_BLOCKS  = (NN + 127) / 128;   // 391
    const int SCAT_BLOCKS = NE / (8 * EPW);     // 18750

    k_init<<<1, 1024>>>();
    const float* cw[4] = {c_W1[0], c_W2[0], c_W1[1], c_W2[1]};
    for (int i = 0; i < 4; i++)
        k_wsplit<<<16, 256>>>(cw[i], whi + (size_t)i * D * D, wlo + (size_t)i * D * D);
    k_pool0<<<ROW_BLOCKS, 256>>>(h, seg, pool, z, c_eps[0]);

    const float* x = h;
    float* youts[2] = {h1, out_h2};
    for (int l = 0; l < 2; l++) {
        k_scatter<<<SCAT_BLOCKS, 256>>>(x, src, dst);
        float* s1 = sums + (l * 2 + 0) * D; float* q1 = sss + (l * 2 + 0) * D;
        float* s2 = sums + (l * 2 + 1) * D; float* q2 = sss + (l * 2 + 1) * D;
        float* w1h = whi + (size_t)(l * 2 + 0) * D * D;
        float* w1l = wlo + (size_t)(l * 2 + 0) * D * D;
        float* w2h = whi + (size_t)(l * 2 + 1) * D * D;
        float* w2l = wlo + (size_t)(l * 2 + 1) * D * D;
        k_gemm<<<GEMM_BLOCKS, 256, SM_TOTAL>>>(z, w1h, w1l, c_b1[l], u,
                                               nullptr, nullptr, nullptr, nullptr,
                                               s1, q1, 0);
        k_gemm<<<GEMM_BLOCKS, 256, SM_TOTAL>>>(u, w2h, w2l, c_b2[l], v,
                                               s1, q1, c_g1[l], c_be1[l],
                                               s2, q2, 1);
        k_out<<<ROW_BLOCKS, 256>>>(v, s2, q2, c_g2[l], c_be2[l],
                                   youts[l], pool + (size_t)(l + 1) * NB * D, seg,
                                   (l == 0) ? z : nullptr,
                                   (l == 0) ? c_eps[1] : nullptr);
        x = h1;
    }
    k_score<<<1, 256>>>(pW[0], pb[0], pW[1], pb[1], pW[2], pb[2], out_sc);
}

// round 9
// speedup vs baseline: 1.4679x; 1.4679x over previous
#include <cuda_runtime.h>
#include <cfloat>

#define NN 50000
#define NE 600000
#define D  128
#define NB 8

// ---------------- scratch (static device memory; no allocs) ----------------
__device__ float g_z [NN * D];
__device__ float g_u [NN * D];
__device__ float g_v [NN * D];
__device__ float g_h1[NN * D];
__device__ float g_sum[4 * D];
__device__ float g_ss [4 * D];
__device__ float g_pool[3 * NB * D];
// frag-packed split-bf16 weights: [w (4)][kc (8)][n (128)][q (4)] float4
__device__ float4 g_wf[4 * 8 * 128 * 4];

__device__ __forceinline__ void atomicMaxFloat(float* addr, float v) {
    if (v >= 0.f) atomicMax((int*)addr, __float_as_int(v));
    else          atomicMin((unsigned int*)addr, __float_as_uint(v));
}

__device__ __forceinline__ void cp16(void* smem, const void* g, int srcsize) {
    unsigned s = (unsigned)__cvta_generic_to_shared(smem);
    asm volatile("cp.async.cg.shared.global [%0], [%1], 16, %2;"
                 :: "r"(s), "l"(g), "r"(srcsize));
}

// pack two f32 into bf16x2 (lo element in low half)
__device__ __forceinline__ unsigned pack_bf16x2(float lo, float hi) {
    unsigned r;
    asm("cvt.rn.bf16x2.f32 %0, %1, %2;" : "=r"(r) : "f"(hi), "f"(lo));
    return r;
}
// split (x0,x1) into bf16x2 hi + bf16x2 residual
__device__ __forceinline__ void split2(float x0, float x1,
                                       unsigned& h, unsigned& l) {
    h = pack_bf16x2(x0, x1);
    float h0 = __uint_as_float(h << 16);
    float h1 = __uint_as_float(h & 0xffff0000u);
    l = pack_bf16x2(x0 - h0, x1 - h1);
}
__device__ __forceinline__ void mma_bf16(float* d, const unsigned* a,
                                         unsigned b0, unsigned b1) {
    asm volatile(
        "mma.sync.aligned.m16n8k16.row.col.f32.bf16.bf16.f32 "
        "{%0,%1,%2,%3}, {%4,%5,%6,%7}, {%8,%9}, {%0,%1,%2,%3};"
        : "+f"(d[0]), "+f"(d[1]), "+f"(d[2]), "+f"(d[3])
        : "r"(a[0]), "r"(a[1]), "r"(a[2]), "r"(a[3]), "r"(b0), "r"(b1));
}

// ---------------- init: zero stats, pool = -FLT_MAX ----------------
__global__ void k_init() {
    int t = threadIdx.x;
    if (t < 4 * D) { g_sum[t] = 0.f; g_ss[t] = 0.f; }
    for (int i = t; i < 3 * NB * D; i += 1024) g_pool[i] = -FLT_MAX;
}

// ---- split all 4 conv weights into frag-packed bf16 hi/lo (one launch) ----
__global__ __launch_bounds__(256) void k_wsplit4(
    const float* __restrict__ w0, const float* __restrict__ w1,
    const float* __restrict__ w2, const float* __restrict__ w3)
{
    int idx = blockIdx.x * 256 + threadIdx.x;   // 0..16383
    const float* ws[4] = {w0, w1, w2, w3};
    const float* W = ws[idx >> 12];
    int i  = idx & 4095;
    int kc = i >> 9;
    int n  = (i >> 2) & 127;
    int q  = i & 3;
    int k0 = kc * 16 + 2 * q;
    float w00 = W[(k0    ) * D + n], w01 = W[(k0 + 1) * D + n];
    float w10 = W[(k0 + 8) * D + n], w11 = W[(k0 + 9) * D + n];
    unsigned bh0, bl0, bh1, bl1;
    split2(w00, w01, bh0, bl0);
    split2(w10, w11, bh1, bl1);
    float4 o;
    o.x = __uint_as_float(bh0); o.y = __uint_as_float(bh1);
    o.z = __uint_as_float(bl0); o.w = __uint_as_float(bl1);
    g_wf[idx] = o;
}

// ------- scatter: z[dst] += x[src]; warp per 4 edges, red.global.v4 --------
#define EPW 4
__global__ __launch_bounds__(256) void k_scatter(const float* __restrict__ x,
                                                 const int* __restrict__ src,
                                                 const int* __restrict__ dst) {
    int warp = (blockIdx.x * 256 + threadIdx.x) >> 5;
    int lane = threadIdx.x & 31;
    int e0   = warp * EPW;
    int4 s4 = *(const int4*)(src + e0);
    int4 d4 = *(const int4*)(dst + e0);
    int ss[EPW] = {s4.x, s4.y, s4.z, s4.w};
    int dd[EPW] = {d4.x, d4.y, d4.z, d4.w};
    float4 v[EPW];
#pragma unroll
    for (int i = 0; i < EPW; i++)
        v[i] = *(const float4*)(x + (size_t)ss[i] * D + lane * 4);
#pragma unroll
    for (int i = 0; i < EPW; i++) {
        float* p = g_z + (size_t)dd[i] * D + lane * 4;
        asm volatile("red.global.add.v4.f32 [%0], {%1, %2, %3, %4};"
                     :: "l"(p), "f"(v[i].x), "f"(v[i].y), "f"(v[i].z), "f"(v[i].w)
                     : "memory");
    }
}

// ------ split-bf16 tensor-core GEMM: 128 rows x 128 cols per block ---------
// out = [relu(bn(A)) if bnrelu else A] @ W + bias; col sum/sumsq accumulated.
#define ASTRIDE 20
#define NCHUNK  8          // K=128 in chunks of 16 (one m16n8k16 step each)
__global__ __launch_bounds__(256) void k_gemm(
    const float* __restrict__ A, const float4* __restrict__ Wf,
    const float* __restrict__ bias, float* __restrict__ out,
    const float* __restrict__ in_sum, const float* __restrict__ in_ss,
    const float* __restrict__ gamma, const float* __restrict__ beta,
    float* __restrict__ out_sum, float* __restrict__ out_ss,
    int bnrelu)
{
    __shared__ float  As[2][128 * ASTRIDE];
    __shared__ float4 WFs[2][512];          // [n(128)][q(4)] per chunk
    __shared__ float  sc_s[128], sh_s[128];

    const int tid  = threadIdx.x;
    const int wid  = tid >> 5;
    const int lane = tid & 31;
    const int gid  = lane >> 2;   // 0..7
    const int qid  = lane & 3;    // 0..3
    const int wm   = (wid >> 1) * 32;
    const int wn   = (wid & 1) * 64;
    const int row0 = blockIdx.x * 128;

    if (bnrelu && tid < 128) {
        float m   = in_sum[tid] * (1.0f / NN);
        float var = in_ss[tid] * (1.0f / NN) - m * m;
        float rs  = rsqrtf(var + 1e-5f);
        float sc  = gamma[tid] * rs;
        sc_s[tid] = sc;
        sh_s[tid] = fmaf(-m, sc, beta[tid]);
    }

    float acc[2][8][4];
#pragma unroll
    for (int mt = 0; mt < 2; mt++)
#pragma unroll
        for (int nt = 0; nt < 8; nt++)
#pragma unroll
            for (int j = 0; j < 4; j++) acc[mt][nt][j] = 0.f;

    const int a_r  = tid >> 2;
    const int a_c4 = (tid & 3) * 4;

#define LOAD_CHUNK(c, b)                                                        \
    {                                                                           \
        _Pragma("unroll")                                                       \
        for (int p = 0; p < 2; p++) {                                           \
            int r = a_r + p * 64;                                               \
            int gr = row0 + r;                                                  \
            const float* gp = A + (size_t)(gr < NN ? gr : 0) * D + (c)*16 + a_c4; \
            cp16(&As[b][r * ASTRIDE + a_c4], gp, gr < NN ? 16 : 0);             \
        }                                                                       \
        cp16(&WFs[b][tid],       Wf + (c) * 512 + tid,       16);               \
        cp16(&WFs[b][tid + 256], Wf + (c) * 512 + tid + 256, 16);               \
        asm volatile("cp.async.commit_group;");                                 \
    }

    LOAD_CHUNK(0, 0);

    for (int c = 0; c < NCHUNK; c++) {
        if (c + 1 < NCHUNK) {
            LOAD_CHUNK(c + 1, (c + 1) & 1);
            asm volatile("cp.async.wait_group 1;");
        } else {
            asm volatile("cp.async.wait_group 0;");
        }
        __syncthreads();
        const int b = c & 1;
        const float*  Ab = As[b];
        const float4* Wb = WFs[b];

        // ---- A fragments (split-bf16) ----
        unsigned ah[2][4], al[2][4];
        float2 sca, sha, scb, shb;
        if (bnrelu) {
            int kg = c * 16 + 2 * qid;
            sca = *(const float2*)&sc_s[kg];     sha = *(const float2*)&sh_s[kg];
            scb = *(const float2*)&sc_s[kg + 8]; shb = *(const float2*)&sh_s[kg + 8];
        }
#pragma unroll
        for (int mt = 0; mt < 2; mt++) {
            int r = wm + 16 * mt + gid;
            float2 p00 = *(const float2*)&Ab[r * ASTRIDE + 2 * qid];
            float2 p10 = *(const float2*)&Ab[(r + 8) * ASTRIDE + 2 * qid];
            float2 p01 = *(const float2*)&Ab[r * ASTRIDE + 2 * qid + 8];
            float2 p11 = *(const float2*)&Ab[(r + 8) * ASTRIDE + 2 * qid + 8];
            if (bnrelu) {
                p00.x = fmaxf(fmaf(p00.x, sca.x, sha.x), 0.f);
                p00.y = fmaxf(fmaf(p00.y, sca.y, sha.y), 0.f);
                p10.x = fmaxf(fmaf(p10.x, sca.x, sha.x), 0.f);
                p10.y = fmaxf(fmaf(p10.y, sca.y, sha.y), 0.f);
                p01.x = fmaxf(fmaf(p01.x, scb.x, shb.x), 0.f);
                p01.y = fmaxf(fmaf(p01.y, scb.y, shb.y), 0.f);
                p11.x = fmaxf(fmaf(p11.x, scb.x, shb.x), 0.f);
                p11.y = fmaxf(fmaf(p11.y, scb.y, shb.y), 0.f);
            }
            split2(p00.x, p00.y, ah[mt][0], al[mt][0]);
            split2(p10.x, p10.y, ah[mt][1], al[mt][1]);
            split2(p01.x, p01.y, ah[mt][2], al[mt][2]);
            split2(p11.x, p11.y, ah[mt][3], al[mt][3]);
        }

        // ---- B fragments: one LDS.128 each; 3 mma per (mt,nt) ----
#pragma unroll
        for (int nt = 0; nt < 8; nt++) {
            float4 f = Wb[(wn + nt * 8 + gid) * 4 + qid];
            unsigned bh0 = __float_as_uint(f.x), bh1 = __float_as_uint(f.y);
            unsigned bl0 = __float_as_uint(f.z), bl1 = __float_as_uint(f.w);
#pragma unroll
            for (int mt = 0; mt < 2; mt++) {
                mma_bf16(acc[mt][nt], al[mt], bh0, bh1);
                mma_bf16(acc[mt][nt], ah[mt], bl0, bl1);
                mma_bf16(acc[mt][nt], ah[mt], bh0, bh1);
            }
        }
        __syncthreads();
    }

    // ---- epilogue: bias, store, column stats ----
#pragma unroll
    for (int nt = 0; nt < 8; nt++) {
        int col = wn + nt * 8 + 2 * qid;
        float2 bb = *(const float2*)(bias + col);
        float s0 = 0.f, s1 = 0.f, q0 = 0.f, q1 = 0.f;
#pragma unroll
        for (int mt = 0; mt < 2; mt++) {
            int r = row0 + wm + 16 * mt + gid;
            float v0 = acc[mt][nt][0] + bb.x;
            float v1 = acc[mt][nt][1] + bb.y;
            float v2 = acc[mt][nt][2] + bb.x;
            float v3 = acc[mt][nt][3] + bb.y;
            if (r < NN) {
                *(float2*)(out + (size_t)r * D + col) = make_float2(v0, v1);
                s0 += v0; s1 += v1; q0 += v0 * v0; q1 += v1 * v1;
            }
            if (r + 8 < NN) {
                *(float2*)(out + (size_t)(r + 8) * D + col) = make_float2(v2, v3);
                s0 += v2; s1 += v3; q0 += v2 * v2; q1 += v3 * v3;
            }
        }
#pragma unroll
        for (int m = 4; m < 32; m <<= 1) {
            s0 += __shfl_xor_sync(0xffffffffu, s0, m);
            s1 += __shfl_xor_sync(0xffffffffu, s1, m);
            q0 += __shfl_xor_sync(0xffffffffu, q0, m);
            q1 += __shfl_xor_sync(0xffffffffu, q1, m);
        }
        if (lane < 4) {
            atomicAdd(&out_sum[col], s0);
            atomicAdd(&out_sum[col + 1], s1);
            atomicAdd(&out_ss[col], q0);
            atomicAdd(&out_ss[col + 1], q1);
        }
    }
}

// -- y = leaky_relu(bn(v)); write y (+ optional znext=(1+eps)*y); pooling ---
__global__ __launch_bounds__(256) void k_out(
    const float* __restrict__ v, const float* __restrict__ in_sum,
    const float* __restrict__ in_ss, const float* __restrict__ gamma,
    const float* __restrict__ beta, float* __restrict__ y,
    float* __restrict__ pool, const int* __restrict__ seg,
    float* __restrict__ znext, const float* __restrict__ eps_next)
{
    __shared__ float sc_s[128], sh_s[128];
    __shared__ int seg_s[128];
    int tid  = threadIdx.x;
    int row0 = blockIdx.x * 128;
    if (tid < 128) {
        float m   = in_sum[tid] * (1.0f / NN);
        float var = in_ss[tid] * (1.0f / NN) - m * m;
        float rs  = rsqrtf(var + 1e-5f);
        float sc  = gamma[tid] * rs;
        sc_s[tid] = sc;
        sh_s[tid] = fmaf(-m, sc, beta[tid]);
        int r = row0 + tid;
        seg_s[tid] = (r < NN) ? seg[r] : -1;
    }
    __syncthreads();
    float es = znext ? (1.0f + *eps_next) : 0.f;
    int c    = tid & 127;
    int rbeg = (tid >> 7) * 64;
    float sc = sc_s[c], sh = sh_s[c];
    float runmax = -FLT_MAX;
    int cur = -1;
    for (int i = 0; i < 64; i++) {
        int r = rbeg + i, gr = row0 + r;
        if (gr >= NN) break;
        float val = fmaf(v[(size_t)gr * D + c], sc, sh);
        val = (val > 0.f) ? val : val * 0.01f;
        y[(size_t)gr * D + c] = val;
        if (znext) znext[(size_t)gr * D + c] = es * val;
        int s = seg_s[r];
        if (s != cur) {
            if (cur >= 0) atomicMaxFloat(&pool[cur * D + c], runmax);
            cur = s; runmax = val;
        } else runmax = fmaxf(runmax, val);
    }
    if (cur >= 0) atomicMaxFloat(&pool[cur * D + c], runmax);
}

// ------ segment-max pooling of raw input h + z init for layer 0 ------------
__global__ __launch_bounds__(256) void k_pool0(const float* __restrict__ x,
                                               const int* __restrict__ seg,
                                               float* __restrict__ pool,
                                               float* __restrict__ z,
                                               const float* __restrict__ epsp)
{
    __shared__ int seg_s[128];
    int tid  = threadIdx.x;
    int row0 = blockIdx.x * 128;
    if (tid < 128) { int r = row0 + tid; seg_s[tid] = (r < NN) ? seg[r] : -1; }
    __syncthreads();
    float es = 1.0f + *epsp;
    int c    = tid & 127;
    int rbeg = (tid >> 7) * 64;
    float runmax = -FLT_MAX;
    int cur = -1;
    for (int i = 0; i < 64; i++) {
        int r = rbeg + i, gr = row0 + r;
        if (gr >= NN) break;
        float val = x[(size_t)gr * D + c];
        z[(size_t)gr * D + c] = es * val;
        int s = seg_s[r];
        if (s != cur) {
            if (cur >= 0) atomicMaxFloat(&pool[cur * D + c], runmax);
            cur = s; runmax = val;
        } else runmax = fmaxf(runmax, val);
    }
    if (cur >= 0) atomicMaxFloat(&pool[cur * D + c], runmax);
}

// -------- score = sum_l pooled_l @ pW_l + pb_l  (8x128, one block) ---------
__global__ __launch_bounds__(256) void k_score(
    const float* __restrict__ W0, const float* __restrict__ b0,
    const float* __restrict__ W1, const float* __restrict__ b1,
    const float* __restrict__ W2, const float* __restrict__ b2,
    float* __restrict__ out)
{
    __shared__ float ps[3 * NB * D];
    int tid = threadIdx.x;
    for (int i = tid; i < 3 * NB * D; i += 256) ps[i] = g_pool[i];
    __syncthreads();
    int b  = tid >> 5;
    int j0 = (tid & 31) * 4;
    float acc[4];
#pragma unroll
    for (int j = 0; j < 4; j++) acc[j] = b0[j0 + j] + b1[j0 + j] + b2[j0 + j];
    const float* Ws[3] = {W0, W1, W2};
    for (int l = 0; l < 3; l++) {
        const float* pl = ps + (l * NB + b) * D;
        const float* Wl = Ws[l];
        for (int k = 0; k < D; k++) {
            float p = pl[k];
            float4 w = *(const float4*)(Wl + (size_t)k * D + j0);
            acc[0] = fmaf(p, w.x, acc[0]);
            acc[1] = fmaf(p, w.y, acc[1]);
            acc[2] = fmaf(p, w.z, acc[2]);
            acc[3] = fmaf(p, w.w, acc[3]);
        }
    }
#pragma unroll
    for (int j = 0; j < 4; j++) out[b * D + j0 + j] = acc[j];
}

// ---------------------------------------------------------------------------
extern "C" void kernel_launch(void* const* d_in, const int* in_sizes, int n_in,
                              void* d_out, int out_size)
{
    const float* h   = (const float*)d_in[0];
    const int*   src = (const int*)d_in[1];
    const int*   dst = (const int*)d_in[2];
    const int*   seg = (const int*)d_in[3];
    const float* c_eps[2] = {(const float*)d_in[4],  (const float*)d_in[13]};
    const float* c_W1 [2] = {(const float*)d_in[5],  (const float*)d_in[14]};
    const float* c_b1 [2] = {(const float*)d_in[6],  (const float*)d_in[15]};
    const float* c_g1 [2] = {(const float*)d_in[7],  (const float*)d_in[16]};
    const float* c_be1[2] = {(const float*)d_in[8],  (const float*)d_in[17]};
    const float* c_W2 [2] = {(const float*)d_in[9],  (const float*)d_in[18]};
    const float* c_b2 [2] = {(const float*)d_in[10], (const float*)d_in[19]};
    const float* c_g2 [2] = {(const float*)d_in[11], (const float*)d_in[20]};
    const float* c_be2[2] = {(const float*)d_in[12], (const float*)d_in[21]};
    const float* pW[3] = {(const float*)d_in[22], (const float*)d_in[24], (const float*)d_in[26]};
    const float* pb[3] = {(const float*)d_in[23], (const float*)d_in[25], (const float*)d_in[27]};

    float* out_h2 = (float*)d_out;
    float* out_sc = (float*)d_out + (size_t)NN * D;

    float *z, *u, *v, *h1, *sums, *sss, *pool;
    float4* wf;
    cudaGetSymbolAddress((void**)&z,    g_z);
    cudaGetSymbolAddress((void**)&u,    g_u);
    cudaGetSymbolAddress((void**)&v,    g_v);
    cudaGetSymbolAddress((void**)&h1,   g_h1);
    cudaGetSymbolAddress((void**)&sums, g_sum);
    cudaGetSymbolAddress((void**)&sss,  g_ss);
    cudaGetSymbolAddress((void**)&pool, g_pool);
    cudaGetSymbolAddress((void**)&wf,   g_wf);

    const int GEMM_BLOCKS = (NN + 127) / 128;   // 391
    const int ROW_BLOCKS  = (NN + 127) / 128;   // 391
    const int SCAT_BLOCKS = NE / (8 * EPW);     // 18750

    k_init<<<1, 1024>>>();
    k_wsplit4<<<64, 256>>>(c_W1[0], c_W2[0], c_W1[1], c_W2[1]);
    k_pool0<<<ROW_BLOCKS, 256>>>(h, seg, pool, z, c_eps[0]);

    const float* x = h;
    float* youts[2] = {h1, out_h2};
    for (int l = 0; l < 2; l++) {
        k_scatter<<<SCAT_BLOCKS, 256>>>(x, src, dst);
        float* s1 = sums + (l * 2 + 0) * D; float* q1 = sss + (l * 2 + 0) * D;
        float* s2 = sums + (l * 2 + 1) * D; float* q2 = sss + (l * 2 + 1) * D;
        const float4* w1f = wf + (size_t)(l * 2 + 0) * 4096;
        const float4* w2f = wf + (size_t)(l * 2 + 1) * 4096;
        k_gemm<<<GEMM_BLOCKS, 256>>>(z, w1f, c_b1[l], u,
                                     nullptr, nullptr, nullptr, nullptr,
                                     s1, q1, 0);
        k_gemm<<<GEMM_BLOCKS, 256>>>(u, w2f, c_b2[l], v,
                                     s1, q1, c_g1[l], c_be1[l],
                                     s2, q2, 1);
        k_out<<<ROW_BLOCKS, 256>>>(v, s2, q2, c_g2[l], c_be2[l],
                                   youts[l], pool + (size_t)(l + 1) * NB * D, seg,
                                   (l == 0) ? z : nullptr,
                                   (l == 0) ? c_eps[1] : nullptr);
        x = h1;
    }
    k_score<<<1, 256>>>(pW[0], pb[0], pW[1], pb[1], pW[2], pb[2], out_sc);
}